// round 10
// baseline (speedup 1.0000x reference)
#include <cuda_runtime.h>

// ---------------------------------------------------------------------------
// LSTM_Model: T=512, B=4096, I=1, H=16, two LSTM layers, then MLP 16->64->32->1
// Reference output = MLP(h2[:, B-1, :]) -> only batch row B-1 matters.
//
// Single fused kernel, 6 warps, SMSP = wid % 4:
//   wid 2 : layer-0 recurrence   (SMSP2, solo)
//   wid 3 : layer-1 recurrence   (SMSP3, solo)
//   wid 0 : layer-1 input-gate precompute (SMSP0)
//   wid 1,4,5 : MLP head, warp-per-row, smem-staged z1 + f32x2 math
//               rows/round: w1:5 (SMSP1), w4:5 (SMSP0), w5:6 (SMSP1)
// Sigmoid-gate weights pre-scaled by 0.5 (chain shortening).
// ---------------------------------------------------------------------------

#define T_STEPS 512
#define H 16
#define BLK 16
#define NB (T_STEPS / BLK)
#define RING 32
#define FULL_MASK 0xffffffffu

typedef unsigned long long ull;

__device__ __forceinline__ float tanh_fast(float x) {
    float y;
    asm("tanh.approx.f32 %0, %1;" : "=f"(y) : "f"(x));
    return y;
}
__device__ __forceinline__ ull pack2(float lo, float hi) {
    ull r;
    asm("mov.b64 %0, {%1, %2};" : "=l"(r) : "f"(lo), "f"(hi));
    return r;
}
__device__ __forceinline__ void unpack2(ull v, float& lo, float& hi) {
    asm("mov.b64 {%0, %1}, %2;" : "=f"(lo), "=f"(hi) : "l"(v));
}
__device__ __forceinline__ ull fma2(ull a, ull b, ull c) {
    ull d;
    asm("fma.rn.f32x2 %0, %1, %2, %3;" : "=l"(d) : "l"(a), "l"(b), "l"(c));
    return d;
}
__device__ __forceinline__ ull add2(ull a, ull b) {
    ull d;
    asm("add.rn.f32x2 %0, %1, %2;" : "=l"(d) : "l"(a), "l"(b));
    return d;
}

// One gate-split LSTM step. Sigmoid-gate weights are PRE-SCALED by 0.5:
//   A = sigma = fma(0.5, tanh(aA), 0.5)  (aA already = (Wh+b)/2)
//   Bv: lower = tanh(aB) (unscaled), upper = sigma (scaled) via cB/dB.
__device__ __forceinline__ void lstm_step(
    float aA, float aB,
    const float* __restrict__ wA,
    const float* __restrict__ wB,
    bool lower, float cB, float dB,
    float& h, float& c)
{
    float s0 = aA,  s1 = 0.0f, s2 = 0.0f, s3 = 0.0f;
    float q0 = aB,  q1 = 0.0f, q2 = 0.0f, q3 = 0.0f;
#pragma unroll
    for (int k = 0; k < H; k += 4) {
        float h0 = __shfl_sync(FULL_MASK, h, k);
        float h1 = __shfl_sync(FULL_MASK, h, k + 1);
        float h2 = __shfl_sync(FULL_MASK, h, k + 2);
        float h3 = __shfl_sync(FULL_MASK, h, k + 3);
        s0 = fmaf(wA[k],     h0, s0);  q0 = fmaf(wB[k],     h0, q0);
        s1 = fmaf(wA[k + 1], h1, s1);  q1 = fmaf(wB[k + 1], h1, q1);
        s2 = fmaf(wA[k + 2], h2, s2);  q2 = fmaf(wB[k + 2], h2, q2);
        s3 = fmaf(wA[k + 3], h3, s3);  q3 = fmaf(wB[k + 3], h3, q3);
    }
    aA = (s0 + s1) + (s2 + s3);
    aB = (q0 + q1) + (q2 + q3);

    float A  = fmaf(0.5f, tanh_fast(aA), 0.5f);    // sigmoid (i / f), pre-scaled
    float Bv = fmaf(cB, tanh_fast(aB), dB);        // tanh g / sigmoid o

    float P  = A * Bv;                          // lower: i*g
    float send1 = lower ? P : A;                // lower sends i*g, upper sends f
    float r1 = __shfl_xor_sync(FULL_MASK, send1, 16);
    float r2 = __shfl_xor_sync(FULL_MASK, Bv, 16);
    float F  = lower ? r1 : A;
    float Pu = lower ? P  : r1;
    c = fmaf(F, c, Pu);
    float tc = tanh_fast(c);
    float O  = lower ? r2 : Bv;
    h = O * tc;
}

// ---------------------------------------------------------------------------
__global__ void __launch_bounds__(192, 1) lstm_fused_kernel(
    const float* __restrict__ x, int B,
    const float* __restrict__ Wih0, const float* __restrict__ Whh0,
    const float* __restrict__ bih0, const float* __restrict__ bhh0,
    const float* __restrict__ Wih1, const float* __restrict__ Whh1,
    const float* __restrict__ bih1, const float* __restrict__ bhh1,
    const float* __restrict__ W1, const float* __restrict__ b1,
    const float* __restrict__ W2, const float* __restrict__ b2,
    const float* __restrict__ W3, const float* __restrict__ b3,
    float* __restrict__ out)
{
    __shared__ float xs[T_STEPS];                       // 2 KB
    __shared__ __align__(16) float h1r[RING * H];       // 2 KB
    __shared__ __align__(16) float xg1r[RING * 64];     // 8 KB
    __shared__ __align__(16) float h2r[RING * H];       // 2 KB
    __shared__ __align__(16) float sz1[3][2][64];       // 1.5 KB MLP z1 stage

    const int tid  = threadIdx.x;
    const int wid  = tid >> 5;
    const int lane = tid & 31;
    const bool lower = (lane < 16);
    const float cB = lower ? 1.0f : 0.5f;
    const float dB = lower ? 0.0f : 0.5f;
    const float sB = lower ? 1.0f : 0.5f;   // B-gate weight pre-scale
    const int l = lane;

    // gather the single relevant batch row of x
    for (int t = tid; t < T_STEPS; t += 192)
        xs[t] = x[(size_t)t * B + (B - 1)];

    // ---------------- per-role setup ----------------
    const bool isL0  = (wid == 2);
    const bool isL1  = (wid == 3);
    const bool isPre = (wid == 0);
    // MLP warps: wid 1 (idx 0, rows 0-4), wid 4 (idx 1, rows 5-9),
    //            wid 5 (idx 2, rows 10-15)
    int mIdx = -1, mStart = 0, mEnd = 0;
    if (wid == 1) { mIdx = 0; mStart = 0;  mEnd = 5;  }
    if (wid == 4) { mIdx = 1; mStart = 5;  mEnd = 10; }
    if (wid == 5) { mIdx = 2; mStart = 10; mEnd = 16; }

    float wA[H], wB[H];                 // recurrence weights
    float uA[H], uB[H];                 // precompute: Wih1 rows
    float bA = 0.0f, bB = 0.0f, wiA = 0.0f, wiB = 0.0f;

    // MLP per-lane packed weights
    ull w1pA[8], w1pB[8], w2p[32];
    float b1a = 0.0f, b1b = 0.0f, b2l = 0.0f, w3l = 0.0f, b3v = 0.0f;

    if (isL0) {
#pragma unroll
        for (int k = 0; k < H; k++) {
            wA[k] = 0.5f * Whh0[l * H + k];
            wB[k] = sB   * Whh0[(l + 32) * H + k];
        }
        wiA = 0.5f * Wih0[l];       wiB = sB * Wih0[l + 32];     // I = 1
        bA  = 0.5f * (bih0[l] + bhh0[l]);
        bB  = sB   * (bih0[l + 32] + bhh0[l + 32]);
    } else if (isPre) {
#pragma unroll
        for (int k = 0; k < H; k++) {
            uA[k] = 0.5f * Wih1[l * H + k];
            uB[k] = sB   * Wih1[(l + 32) * H + k];
        }
        bA = 0.5f * (bih1[l] + bhh1[l]);
        bB = sB   * (bih1[l + 32] + bhh1[l + 32]);
    } else if (isL1) {
#pragma unroll
        for (int k = 0; k < H; k++) {
            wA[k] = 0.5f * Whh1[l * H + k];
            wB[k] = sB   * Whh1[(l + 32) * H + k];
        }
    } else {  // MLP warps
#pragma unroll
        for (int k = 0; k < 8; k++) {
            w1pA[k] = pack2(W1[l * H + 2*k],        W1[l * H + 2*k + 1]);
            w1pB[k] = pack2(W1[(l + 32) * H + 2*k], W1[(l + 32) * H + 2*k + 1]);
        }
#pragma unroll
        for (int k = 0; k < 32; k++)
            w2p[k] = pack2(W2[l * 64 + 2*k], W2[l * 64 + 2*k + 1]);
        b1a = b1[l];  b1b = b1[l + 32];
        b2l = b2[l];  w3l = W3[l];  b3v = b3[0];
    }
    __syncthreads();

    float h = 0.0f, c = 0.0f;

    // rounds: L0 does block blk, Pre blk-1, L1 blk-2, MLP blk-3
    for (int blk = 0; blk < NB + 3; blk++) {
        if (isL0) {
            if (blk < NB) {
                const int t0 = blk * BLK;
#pragma unroll 1
                for (int s = 0; s < BLK; s++) {
                    const int t = t0 + s;
                    const float xt = xs[t];
                    lstm_step(fmaf(wiA, xt, bA), fmaf(wiB, xt, bB),
                              wA, wB, lower, cB, dB, h, c);
                    if (lower) h1r[(t & (RING-1)) * H + lane] = h;
                }
            }
        } else if (isPre) {
            if (blk >= 1 && blk <= NB) {
                const int t0 = (blk - 1) * BLK;
#pragma unroll 1
                for (int s = 0; s < BLK; s++) {
                    const int t = t0 + s;
                    const float4* hp =
                        reinterpret_cast<const float4*>(h1r + (t & (RING-1)) * H);
                    float a = bA, b = bB;
#pragma unroll
                    for (int q = 0; q < 4; q++) {
                        float4 h4 = hp[q];
                        a = fmaf(uA[q*4+0], h4.x, a);  b = fmaf(uB[q*4+0], h4.x, b);
                        a = fmaf(uA[q*4+1], h4.y, a);  b = fmaf(uB[q*4+1], h4.y, b);
                        a = fmaf(uA[q*4+2], h4.z, a);  b = fmaf(uB[q*4+2], h4.z, b);
                        a = fmaf(uA[q*4+3], h4.w, a);  b = fmaf(uB[q*4+3], h4.w, b);
                    }
                    xg1r[(t & (RING-1)) * 64 + l]      = a;
                    xg1r[(t & (RING-1)) * 64 + l + 32] = b;
                }
            }
        } else if (isL1) {
            if (blk >= 2 && blk <= NB + 1) {
                const int t0 = (blk - 2) * BLK;
#pragma unroll 1
                for (int s = 0; s < BLK; s++) {
                    const int t = t0 + s;
                    lstm_step(xg1r[(t & (RING-1)) * 64 + l],
                              xg1r[(t & (RING-1)) * 64 + l + 32],
                              wA, wB, lower, cB, dB, h, c);
                    if (lower) h2r[(t & (RING-1)) * H + lane] = h;
                }
            }
        } else if (mIdx >= 0) {  // MLP warps, rows of block blk-3
            if (blk >= 3) {
                const int t0 = (blk - 3) * BLK;
#pragma unroll 1
                for (int s = mStart; s < mEnd; s++) {
                    const int r = t0 + s;
                    // load h row as 8 packed f32x2
                    const ulonglong2* hp =
                        reinterpret_cast<const ulonglong2*>(h2r + (r & (RING-1)) * H);
                    ull hp8[8];
#pragma unroll
                    for (int q = 0; q < 4; q++) {
                        ulonglong2 v = hp[q];
                        hp8[2*q] = v.x;  hp8[2*q+1] = v.y;
                    }
                    // z1 gates l and l+32 (packed fma, dual accumulators)
                    ull aA0 = 0, aA1 = 0, aB0 = 0, aB1 = 0;
#pragma unroll
                    for (int k = 0; k < 8; k += 2) {
                        aA0 = fma2(w1pA[k],   hp8[k],   aA0);
                        aA1 = fma2(w1pA[k+1], hp8[k+1], aA1);
                        aB0 = fma2(w1pB[k],   hp8[k],   aB0);
                        aB1 = fma2(w1pB[k+1], hp8[k+1], aB1);
                    }
                    float lo, hi;
                    unpack2(add2(aA0, aA1), lo, hi);
                    float z1a = fmaxf(b1a + lo + hi, 0.0f);
                    unpack2(add2(aB0, aB1), lo, hi);
                    float z1b = fmaxf(b1b + lo + hi, 0.0f);

                    float* stage = sz1[mIdx][s & 1];
                    stage[l]      = z1a;
                    stage[l + 32] = z1b;
                    __syncwarp();

                    // z2 gate l: 64-dot via broadcast LDS.128 + packed fma
                    const ulonglong2* zp = reinterpret_cast<const ulonglong2*>(stage);
                    ull a0 = 0, a1 = 0, a2 = 0, a3 = 0;
#pragma unroll
                    for (int q = 0; q < 16; q += 2) {
                        ulonglong2 v0 = zp[q];
                        ulonglong2 v1 = zp[q + 1];
                        a0 = fma2(w2p[2*q],     v0.x, a0);
                        a1 = fma2(w2p[2*q + 1], v0.y, a1);
                        a2 = fma2(w2p[2*q + 2], v1.x, a2);
                        a3 = fma2(w2p[2*q + 3], v1.y, a3);
                    }
                    unpack2(add2(add2(a0, a1), add2(a2, a3)), lo, hi);
                    float z2v = fmaxf(b2l + lo + hi, 0.0f);

                    // final dot: butterfly reduce of w3l * z2v
                    float p = w3l * z2v;
                    p += __shfl_xor_sync(FULL_MASK, p, 16);
                    p += __shfl_xor_sync(FULL_MASK, p, 8);
                    p += __shfl_xor_sync(FULL_MASK, p, 4);
                    p += __shfl_xor_sync(FULL_MASK, p, 2);
                    p += __shfl_xor_sync(FULL_MASK, p, 1);
                    if (lane == 0) out[r] = p + b3v;
                }
            }
        }
        __syncthreads();   // uniform: all 192 threads, every round; drains STS
    }
}

// ---------------------------------------------------------------------------
extern "C" void kernel_launch(void* const* d_in, const int* in_sizes, int n_in,
                              void* d_out, int out_size)
{
    const float* x    = (const float*)d_in[0];
    const float* Wih0 = (const float*)d_in[1];
    const float* Whh0 = (const float*)d_in[2];
    const float* bih0 = (const float*)d_in[3];
    const float* bhh0 = (const float*)d_in[4];
    const float* Wih1 = (const float*)d_in[5];
    const float* Whh1 = (const float*)d_in[6];
    const float* bih1 = (const float*)d_in[7];
    const float* bhh1 = (const float*)d_in[8];
    const float* W1   = (const float*)d_in[9];
    const float* b1   = (const float*)d_in[10];
    const float* W2   = (const float*)d_in[11];
    const float* b2   = (const float*)d_in[12];
    const float* W3   = (const float*)d_in[13];
    const float* b3   = (const float*)d_in[14];

    const int B = in_sizes[0] / T_STEPS;   // 4096 (I = 1)

    lstm_fused_kernel<<<1, 192>>>(x, B,
        Wih0, Whh0, bih0, bhh0, Wih1, Whh1, bih1, bhh1,
        W1, b1, W2, b2, W3, b3, (float*)d_out);
}

// round 12
// speedup vs baseline: 1.1656x; 1.1656x over previous
#include <cuda_runtime.h>

// ---------------------------------------------------------------------------
// LSTM_Model: T=512, B=4096, I=1, H=16, two LSTM layers, then MLP 16->64->32->1
// Reference output = MLP(h2[:, B-1, :]) -> only batch row B-1 matters.
//
// Single fused kernel, 6 warps, SMSP = wid % 4:
//   wid 2 : layer-0 recurrence   (SMSP2, solo)
//   wid 3 : layer-1 recurrence   (SMSP3, solo)
//   wid 0 : layer-1 input-gate precompute (SMSP0)
//   wid 1,4,5 : MLP head (warp-per-row)
// LSTM state (h,c) lives ONLY on upper half-warp (lanes 16-31); lower half
// computes (i,g) and ships i*g across via one xor-shfl. No SELs, no 2nd
// exchange on the critical chain. Sigmoid-gate weights pre-scaled by 0.5.
// ---------------------------------------------------------------------------

#define T_STEPS 512
#define H 16
#define BLK 16
#define NB (T_STEPS / BLK)
#define RING 32
#define FULL_MASK 0xffffffffu

typedef unsigned long long ull;

__device__ __forceinline__ float tanh_fast(float x) {
    float y;
    asm("tanh.approx.f32 %0, %1;" : "=f"(y) : "f"(x));
    return y;
}
__device__ __forceinline__ ull pack2(float lo, float hi) {
    ull r;
    asm("mov.b64 %0, {%1, %2};" : "=l"(r) : "f"(lo), "f"(hi));
    return r;
}
__device__ __forceinline__ void unpack2(ull v, float& lo, float& hi) {
    asm("mov.b64 {%0, %1}, %2;" : "=f"(lo), "=f"(hi) : "l"(v));
}
__device__ __forceinline__ ull fma2(ull a, ull b, ull c) {
    ull d;
    asm("fma.rn.f32x2 %0, %1, %2, %3;" : "=l"(d) : "l"(a), "l"(b), "l"(c));
    return d;
}
__device__ __forceinline__ ull add2(ull a, ull b) {
    ull d;
    asm("add.rn.f32x2 %0, %1, %2;" : "=l"(d) : "l"(a), "l"(b));
    return d;
}

// One LSTM step, state on upper half only.
//   lower lane j   : gates i (row j,    pre-scaled 0.5) and g (row j+32)
//   upper lane j+16: gates f (row j+16, pre-scaled 0.5) and o (row j+48, 0.5)
// h for unit k is read from lane 16+k. After the single xor-16 exchange,
// upper half updates (c, h); lower half's c/h are garbage and never read.
__device__ __forceinline__ void lstm_step(
    float aA, float aB,
    const float* __restrict__ wA,
    const float* __restrict__ wB,
    float cB, float dB,
    float& h, float& c)
{
    float s0 = aA,  s1 = 0.0f, s2 = 0.0f, s3 = 0.0f;
    float q0 = aB,  q1 = 0.0f, q2 = 0.0f, q3 = 0.0f;
#pragma unroll
    for (int k = 0; k < H; k += 4) {
        float h0 = __shfl_sync(FULL_MASK, h, 16 + k);
        float h1 = __shfl_sync(FULL_MASK, h, 16 + k + 1);
        float h2 = __shfl_sync(FULL_MASK, h, 16 + k + 2);
        float h3 = __shfl_sync(FULL_MASK, h, 16 + k + 3);
        s0 = fmaf(wA[k],     h0, s0);  q0 = fmaf(wB[k],     h0, q0);
        s1 = fmaf(wA[k + 1], h1, s1);  q1 = fmaf(wB[k + 1], h1, q1);
        s2 = fmaf(wA[k + 2], h2, s2);  q2 = fmaf(wB[k + 2], h2, q2);
        s3 = fmaf(wA[k + 3], h3, s3);  q3 = fmaf(wB[k + 3], h3, q3);
    }
    aA = (s0 + s1) + (s2 + s3);
    aB = (q0 + q1) + (q2 + q3);

    float A  = fmaf(0.5f, tanh_fast(aA), 0.5f);   // lower: sigma(i), upper: sigma(f)
    float Bv = fmaf(cB, tanh_fast(aB), dB);       // lower: tanh(g),  upper: sigma(o)

    float P  = A * Bv;                            // lower: i*g (upper: f*o, unused)
    float r1 = __shfl_xor_sync(FULL_MASK, P, 16); // upper receives i*g
    c = fmaf(A, c, r1);                           // upper: sigma(f)*c + i*g
    h = Bv * tanh_fast(c);                        // upper: sigma(o)*tanh(c)
}

// ---------------------------------------------------------------------------
__global__ void __launch_bounds__(192, 1) lstm_fused_kernel(
    const float* __restrict__ x, int B,
    const float* __restrict__ Wih0, const float* __restrict__ Whh0,
    const float* __restrict__ bih0, const float* __restrict__ bhh0,
    const float* __restrict__ Wih1, const float* __restrict__ Whh1,
    const float* __restrict__ bih1, const float* __restrict__ bhh1,
    const float* __restrict__ W1, const float* __restrict__ b1,
    const float* __restrict__ W2, const float* __restrict__ b2,
    const float* __restrict__ W3, const float* __restrict__ b3,
    float* __restrict__ out)
{
    __shared__ float xs[T_STEPS];                       // 2 KB
    __shared__ __align__(16) float h1r[RING * H];       // 2 KB
    __shared__ __align__(16) float xg1r[RING * 64];     // 8 KB
    __shared__ __align__(16) float h2r[RING * H];       // 2 KB
    __shared__ __align__(16) float sz1[3][2][64];       // 1.5 KB MLP z1 stage

    const int tid  = threadIdx.x;
    const int wid  = tid >> 5;
    const int lane = tid & 31;
    const bool lower = (lane < 16);
    const float cB = lower ? 1.0f : 0.5f;
    const float dB = lower ? 0.0f : 0.5f;
    const float sB = lower ? 1.0f : 0.5f;   // B-gate weight pre-scale
    const int l = lane;

    // gather the single relevant batch row of x
    for (int t = tid; t < T_STEPS; t += 192)
        xs[t] = x[(size_t)t * B + (B - 1)];

    // ---------------- per-role setup ----------------
    const bool isL0  = (wid == 2);
    const bool isL1  = (wid == 3);
    const bool isPre = (wid == 0);
    int mIdx = -1, mStart = 0, mEnd = 0;
    if (wid == 1) { mIdx = 0; mStart = 0;  mEnd = 5;  }
    if (wid == 4) { mIdx = 1; mStart = 5;  mEnd = 10; }
    if (wid == 5) { mIdx = 2; mStart = 10; mEnd = 16; }

    float wA[H], wB[H];                 // recurrence weights
    float uA[H], uB[H];                 // precompute: Wih1 rows
    float bA = 0.0f, bB = 0.0f, wiA = 0.0f, wiB = 0.0f;

    // MLP per-lane packed weights
    ull w1pA[8], w1pB[8], w2p[32];
    float b1a = 0.0f, b1b = 0.0f, b2l = 0.0f, w3l = 0.0f, b3v = 0.0f;

    if (isL0) {
#pragma unroll
        for (int k = 0; k < H; k++) {
            wA[k] = 0.5f * Whh0[l * H + k];
            wB[k] = sB   * Whh0[(l + 32) * H + k];
        }
        wiA = 0.5f * Wih0[l];       wiB = sB * Wih0[l + 32];     // I = 1
        bA  = 0.5f * (bih0[l] + bhh0[l]);
        bB  = sB   * (bih0[l + 32] + bhh0[l + 32]);
    } else if (isPre) {
#pragma unroll
        for (int k = 0; k < H; k++) {
            uA[k] = 0.5f * Wih1[l * H + k];
            uB[k] = sB   * Wih1[(l + 32) * H + k];
        }
        bA = 0.5f * (bih1[l] + bhh1[l]);
        bB = sB   * (bih1[l + 32] + bhh1[l + 32]);
    } else if (isL1) {
#pragma unroll
        for (int k = 0; k < H; k++) {
            wA[k] = 0.5f * Whh1[l * H + k];
            wB[k] = sB   * Whh1[(l + 32) * H + k];
        }
    } else {  // MLP warps
#pragma unroll
        for (int k = 0; k < 8; k++) {
            w1pA[k] = pack2(W1[l * H + 2*k],        W1[l * H + 2*k + 1]);
            w1pB[k] = pack2(W1[(l + 32) * H + 2*k], W1[(l + 32) * H + 2*k + 1]);
        }
#pragma unroll
        for (int k = 0; k < 32; k++)
            w2p[k] = pack2(W2[l * 64 + 2*k], W2[l * 64 + 2*k + 1]);
        b1a = b1[l];  b1b = b1[l + 32];
        b2l = b2[l];  w3l = W3[l];  b3v = b3[0];
    }
    __syncthreads();

    float h = 0.0f, c = 0.0f;

    // rounds: L0 does block blk, Pre blk-1, L1 blk-2, MLP blk-3
    for (int blk = 0; blk < NB + 3; blk++) {
        if (isL0) {
            if (blk < NB) {
                const int t0 = blk * BLK;
#pragma unroll 4
                for (int s = 0; s < BLK; s++) {
                    const int t = t0 + s;
                    const float xt = xs[t];
                    lstm_step(fmaf(wiA, xt, bA), fmaf(wiB, xt, bB),
                              wA, wB, cB, dB, h, c);
                    if (!lower) h1r[(t & (RING-1)) * H + (lane - 16)] = h;
                }
            }
        } else if (isPre) {
            if (blk >= 1 && blk <= NB) {
                const int t0 = (blk - 1) * BLK;
#pragma unroll 4
                for (int s = 0; s < BLK; s++) {
                    const int t = t0 + s;
                    const float4* hp =
                        reinterpret_cast<const float4*>(h1r + (t & (RING-1)) * H);
                    float a = bA, b = bB;
#pragma unroll
                    for (int q = 0; q < 4; q++) {
                        float4 h4 = hp[q];
                        a = fmaf(uA[q*4+0], h4.x, a);  b = fmaf(uB[q*4+0], h4.x, b);
                        a = fmaf(uA[q*4+1], h4.y, a);  b = fmaf(uB[q*4+1], h4.y, b);
                        a = fmaf(uA[q*4+2], h4.z, a);  b = fmaf(uB[q*4+2], h4.z, b);
                        a = fmaf(uA[q*4+3], h4.w, a);  b = fmaf(uB[q*4+3], h4.w, b);
                    }
                    xg1r[(t & (RING-1)) * 64 + l]      = a;
                    xg1r[(t & (RING-1)) * 64 + l + 32] = b;
                }
            }
        } else if (isL1) {
            if (blk >= 2 && blk <= NB + 1) {
                const int t0 = (blk - 2) * BLK;
#pragma unroll 4
                for (int s = 0; s < BLK; s++) {
                    const int t = t0 + s;
                    lstm_step(xg1r[(t & (RING-1)) * 64 + l],
                              xg1r[(t & (RING-1)) * 64 + l + 32],
                              wA, wB, cB, dB, h, c);
                    if (!lower) h2r[(t & (RING-1)) * H + (lane - 16)] = h;
                }
            }
        } else if (mIdx >= 0) {  // MLP warps, rows of block blk-3
            if (blk >= 3) {
                const int t0 = (blk - 3) * BLK;
#pragma unroll 1
                for (int s = mStart; s < mEnd; s++) {
                    const int r = t0 + s;
                    const ulonglong2* hp =
                        reinterpret_cast<const ulonglong2*>(h2r + (r & (RING-1)) * H);
                    ull hp8[8];
#pragma unroll
                    for (int q = 0; q < 4; q++) {
                        ulonglong2 v = hp[q];
                        hp8[2*q] = v.x;  hp8[2*q+1] = v.y;
                    }
                    // z1 gates l and l+32 (packed fma, dual accumulators)
                    ull aA0 = 0, aA1 = 0, aB0 = 0, aB1 = 0;
#pragma unroll
                    for (int k = 0; k < 8; k += 2) {
                        aA0 = fma2(w1pA[k],   hp8[k],   aA0);
                        aA1 = fma2(w1pA[k+1], hp8[k+1], aA1);
                        aB0 = fma2(w1pB[k],   hp8[k],   aB0);
                        aB1 = fma2(w1pB[k+1], hp8[k+1], aB1);
                    }
                    float lo, hi;
                    unpack2(add2(aA0, aA1), lo, hi);
                    float z1a = fmaxf(b1a + lo + hi, 0.0f);
                    unpack2(add2(aB0, aB1), lo, hi);
                    float z1b = fmaxf(b1b + lo + hi, 0.0f);

                    float* stage = sz1[mIdx][s & 1];
                    stage[l]      = z1a;
                    stage[l + 32] = z1b;
                    __syncwarp();

                    // z2 gate l: 64-dot via broadcast LDS.128 + packed fma
                    const ulonglong2* zp = reinterpret_cast<const ulonglong2*>(stage);
                    ull a0 = 0, a1 = 0, a2 = 0, a3 = 0;
#pragma unroll
                    for (int q = 0; q < 16; q += 2) {
                        ulonglong2 v0 = zp[q];
                        ulonglong2 v1 = zp[q + 1];
                        a0 = fma2(w2p[2*q],     v0.x, a0);
                        a1 = fma2(w2p[2*q + 1], v0.y, a1);
                        a2 = fma2(w2p[2*q + 2], v1.x, a2);
                        a3 = fma2(w2p[2*q + 3], v1.y, a3);
                    }
                    unpack2(add2(add2(a0, a1), add2(a2, a3)), lo, hi);
                    float z2v = fmaxf(b2l + lo + hi, 0.0f);

                    // final dot: butterfly reduce of w3l * z2v
                    float p = w3l * z2v;
                    p += __shfl_xor_sync(FULL_MASK, p, 16);
                    p += __shfl_xor_sync(FULL_MASK, p, 8);
                    p += __shfl_xor_sync(FULL_MASK, p, 4);
                    p += __shfl_xor_sync(FULL_MASK, p, 2);
                    p += __shfl_xor_sync(FULL_MASK, p, 1);
                    if (lane == 0) out[r] = p + b3v;
                }
            }
        }
        __syncthreads();   // uniform: all 192 threads, every round; drains STS
    }
}

// ---------------------------------------------------------------------------
extern "C" void kernel_launch(void* const* d_in, const int* in_sizes, int n_in,
                              void* d_out, int out_size)
{
    const float* x    = (const float*)d_in[0];
    const float* Wih0 = (const float*)d_in[1];
    const float* Whh0 = (const float*)d_in[2];
    const float* bih0 = (const float*)d_in[3];
    const float* bhh0 = (const float*)d_in[4];
    const float* Wih1 = (const float*)d_in[5];
    const float* Whh1 = (const float*)d_in[6];
    const float* bih1 = (const float*)d_in[7];
    const float* bhh1 = (const float*)d_in[8];
    const float* W1   = (const float*)d_in[9];
    const float* b1   = (const float*)d_in[10];
    const float* W2   = (const float*)d_in[11];
    const float* b2   = (const float*)d_in[12];
    const float* W3   = (const float*)d_in[13];
    const float* b3   = (const float*)d_in[14];

    const int B = in_sizes[0] / T_STEPS;   // 4096 (I = 1)

    lstm_fused_kernel<<<1, 192>>>(x, B,
        Wih0, Whh0, bih0, bhh0, Wih1, Whh1, bih1, bhh1,
        W1, b1, W2, b2, W3, b3, (float*)d_out);
}